// round 10
// baseline (speedup 1.0000x reference)
#include <cuda_runtime.h>
#include <cuda_bf16.h>
#include <cstdint>

// Fixed problem shapes
#define NB 4
#define NT 2048
#define NC 1024
#define NH 16
#define DH 64
#define NM (NB*NT)   // 8192 rows

typedef unsigned short ush;

// Scratch (allocation-free rule: __device__ globals)
__device__ ush g_xh[(size_t)NM*NC], g_xl[(size_t)NM*NC];
__device__ ush g_wh[(size_t)4*NC*NC], g_wl[(size_t)4*NC*NC];
__device__ ush g_qh[(size_t)NB*NH*NT*DH], g_ql[(size_t)NB*NH*NT*DH];
__device__ ush g_kh[(size_t)NB*NH*NT*DH], g_kl[(size_t)NB*NH*NT*DH];
__device__ ush g_vh[(size_t)NB*NH*NT*DH], g_vl[(size_t)NB*NH*NT*DH];
__device__ ush g_ah[(size_t)NM*NC], g_al[(size_t)NM*NC];

__device__ __forceinline__ void split_pack(float x, float y,
                                           uint32_t &hi, uint32_t &lo) {
    __nv_bfloat16 hx = __float2bfloat16_rn(x), hy = __float2bfloat16_rn(y);
    float fx = __bfloat162float(hx), fy = __bfloat162float(hy);
    __nv_bfloat16 lx = __float2bfloat16_rn(x - fx), ly = __float2bfloat16_rn(y - fy);
    hi = ((uint32_t)__bfloat16_as_ushort(hy) << 16) | __bfloat16_as_ushort(hx);
    lo = ((uint32_t)__bfloat16_as_ushort(ly) << 16) | __bfloat16_as_ushort(lx);
}

#define MMA_BF16(d, a0,a1,a2,a3, b0,b1) \
    asm volatile("mma.sync.aligned.m16n8k16.row.col.f32.bf16.bf16.f32 " \
        "{%0,%1,%2,%3}, {%4,%5,%6,%7}, {%8,%9}, {%0,%1,%2,%3};" \
        : "+f"(d[0]), "+f"(d[1]), "+f"(d[2]), "+f"(d[3]) \
        : "r"(a0), "r"(a1), "r"(a2), "r"(a3), "r"(b0), "r"(b1))

#define LDSM4(R0,R1,R2,R3,ADDR) \
    asm volatile("ldmatrix.sync.aligned.m8n8.x4.shared.b16 {%0,%1,%2,%3}, [%4];" \
        : "=r"(R0), "=r"(R1), "=r"(R2), "=r"(R3) : "r"(ADDR))
#define LDSM4T(R0,R1,R2,R3,ADDR) \
    asm volatile("ldmatrix.sync.aligned.m8n8.x4.trans.shared.b16 {%0,%1,%2,%3}, [%4];" \
        : "=r"(R0), "=r"(R1), "=r"(R2), "=r"(R3) : "r"(ADDR))

#define CP16(saddr, gptr) \
    asm volatile("cp.async.cg.shared.global [%0], [%1], 16;" \
                 :: "r"(saddr), "l"(gptr) : "memory")
#define CP_COMMIT() asm volatile("cp.async.commit_group;" ::: "memory")
#define CP_WAIT1()  asm volatile("cp.async.wait_group 1;" ::: "memory")
#define CP_WAIT0()  asm volatile("cp.async.wait_group 0;" ::: "memory")

// ===========================================================================
// One-shot fp32 -> bf16 hi/lo conversion (Wq pre-scaled by sqrt(HS)=8).
// ===========================================================================
#define N4X ((size_t)NM*NC/4)
#define N4W ((size_t)NC*NC/4)

__global__ __launch_bounds__(256) void convert_kernel(
    const float* __restrict__ x,  const float* __restrict__ Wq,
    const float* __restrict__ Wk, const float* __restrict__ Wv,
    const float* __restrict__ Wo)
{
    const size_t i = (size_t)blockIdx.x * blockDim.x + threadIdx.x;
    const float* src;
    ush *dh, *dl;
    float sc = 1.0f;
    if (i < N4X) {
        src = x + i*4; dh = g_xh + i*4; dl = g_xl + i*4;
    } else {
        size_t j = i - N4X;
        size_t w = j / N4W, r = j % N4W;
        const float* ws[4] = {Wq, Wk, Wv, Wo};
        src = ws[w] + r*4;
        dh = g_wh + w*(size_t)NC*NC + r*4;
        dl = g_wl + w*(size_t)NC*NC + r*4;
        if (w == 0) sc = 8.0f;
    }
    float4 v = *(const float4*)src;
    uint32_t h0, l0, h1, l1;
    split_pack(v.x*sc, v.y*sc, h0, l0);
    split_pack(v.z*sc, v.w*sc, h1, l1);
    *(uint32_t*)(dh)   = h0;  *(uint32_t*)(dh+2) = h1;
    *(uint32_t*)(dl)   = l0;  *(uint32_t*)(dl+2) = l1;
}

// ===========================================================================
// 3xBF16 GEMM: 3-stage cp.async pipeline, XOR-swizzled smem (no padding),
// single __syncthreads per K-chunk. C[M,N] = A[M,K]*B[N,K]^T.
// Swizzle (64B rows, 4x16B chunks): phys_chunk = c ^ ((row>>1)&3).
// ===========================================================================
#define BM 128
#define BN 128
#define BK2 32
#define NCHUNK (NC/BK2)        // 32
#define PLB2 8192              // plane bytes: 128 rows * 64B
#define STAGE_B (4*PLB2)       // 32768
#define GEMM_SMEM (3*STAGE_B)  // 98304

__global__ __launch_bounds__(256) void gemm_bf16(
    const float* __restrict__ bias,
    float* __restrict__ Cout,
    int mode)
{
    extern __shared__ ush sm[];

    const int tid  = threadIdx.x;
    const int wid  = tid >> 5;
    const int lane = tid & 31;
    const int warp_m = wid >> 2;
    const int warp_n = wid & 3;
    const int qr = lane >> 2;
    const int qc = lane & 3;

    const int row0 = blockIdx.y * BM;
    const int col0 = blockIdx.x * BN;

    const ush *Ah, *Al, *Wh, *Wl;
    ush *outh = 0, *outl = 0;
    if (mode == 0) {
        Ah = g_xh; Al = g_xl;
        const size_t wo = (size_t)blockIdx.z * NC * NC;
        Wh = g_wh + wo; Wl = g_wl + wo;
        if (blockIdx.z == 0)      { outh = g_qh; outl = g_ql; }
        else if (blockIdx.z == 1) { outh = g_kh; outl = g_kl; }
        else                      { outh = g_vh; outl = g_vl; }
    } else {
        Ah = g_ah; Al = g_al;
        Wh = g_wh + (size_t)3*NC*NC; Wl = g_wl + (size_t)3*NC*NC;
    }

    // loader: thread t -> row t>>1, chunks c0=2*(t&1), c0+1 (each 16B)
    const int r   = tid >> 1;
    const int c0  = (tid & 1) * 2;
    const uint32_t sx = ((uint32_t)r >> 1) & 3;
    const uint32_t p0 = (uint32_t)((c0     ^ sx) << 4);
    const uint32_t p1 = (uint32_t)(((c0+1) ^ sx) << 4);
    const ush* gAh = Ah + (size_t)(row0 + r)*NC + c0*8;
    const ush* gAl = Al + (size_t)(row0 + r)*NC + c0*8;
    const ush* gBh = Wh + (size_t)(col0 + r)*NC + c0*8;
    const ush* gBl = Wl + (size_t)(col0 + r)*NC + c0*8;
    const uint32_t sbase = (uint32_t)__cvta_generic_to_shared(sm);
    const uint32_t rowb  = (uint32_t)r * 64;

    auto load_stage = [&](int c, int s) {
        const uint32_t st = sbase + (uint32_t)s*STAGE_B + rowb;
        const int g = c * BK2;
        CP16(st + p0,           gAh + g);  CP16(st + p1,           gAh + g + 8);
        CP16(st + PLB2 + p0,    gAl + g);  CP16(st + PLB2 + p1,    gAl + g + 8);
        CP16(st + 2*PLB2 + p0,  gBh + g);  CP16(st + 2*PLB2 + p1,  gBh + g + 8);
        CP16(st + 3*PLB2 + p0,  gBl + g);  CP16(st + 3*PLB2 + p1,  gBl + g + 8);
        CP_COMMIT();
    };

    // ldmatrix per-lane offsets (swizzled, within a plane)
    const uint32_t ra = (uint32_t)(warp_m*64 + (lane & 15));
    const uint32_t a_off = ra*64 + ((((uint32_t)(lane >> 4)) ^ ((ra >> 1) & 3)) << 4);
    const uint32_t rb = (uint32_t)(warp_n*32 + ((lane & 16) >> 1) + (lane & 7));
    const uint32_t b_off = rb*64 + ((((uint32_t)((lane & 8) >> 3)) ^ ((rb >> 1) & 3)) << 4);

    float acc[4][4][4] = {};

    load_stage(0, 0);
    load_stage(1, 1);

    for (int c = 0; c < NCHUNK; c++) {
        if (c + 1 < NCHUNK) { CP_WAIT1(); } else { CP_WAIT0(); }
        __syncthreads();
        if (c + 2 < NCHUNK) load_stage(c + 2, (c + 2) % 3);

        const uint32_t sb = sbase + (uint32_t)(c % 3)*STAGE_B;

        #pragma unroll
        for (int kk = 0; kk < 2; kk++) {
            const uint32_t kx = (uint32_t)kk << 5;
            uint32_t A0[4][4], A1[4][4], B0[2][4], B1[2][4];
            #pragma unroll
            for (int mi = 0; mi < 4; mi++) {
                const uint32_t ao = (sb + a_off + (uint32_t)mi*1024) ^ kx;
                LDSM4(A0[mi][0],A0[mi][1],A0[mi][2],A0[mi][3], ao);
                LDSM4(A1[mi][0],A1[mi][1],A1[mi][2],A1[mi][3], ao + PLB2);
            }
            #pragma unroll
            for (int np = 0; np < 2; np++) {
                const uint32_t bo = (sb + 2*PLB2 + b_off + (uint32_t)np*1024) ^ kx;
                LDSM4(B0[np][0],B0[np][1],B0[np][2],B0[np][3], bo);
                LDSM4(B1[np][0],B1[np][1],B1[np][2],B1[np][3], bo + PLB2);
            }
            #pragma unroll
            for (int mi = 0; mi < 4; mi++)
                #pragma unroll
                for (int ni = 0; ni < 4; ni++) {
                    const int np = ni >> 1, j = (ni & 1) * 2;
                    MMA_BF16(acc[mi][ni], A0[mi][0],A0[mi][1],A0[mi][2],A0[mi][3], B0[np][j],B0[np][j+1]);
                    MMA_BF16(acc[mi][ni], A1[mi][0],A1[mi][1],A1[mi][2],A1[mi][3], B0[np][j],B0[np][j+1]);
                    MMA_BF16(acc[mi][ni], A0[mi][0],A0[mi][1],A0[mi][2],A0[mi][3], B1[np][j],B1[np][j+1]);
                }
        }
    }

    #pragma unroll
    for (int mi = 0; mi < 4; mi++) {
        const int m0 = row0 + warp_m*64 + mi*16 + qr;
        #pragma unroll
        for (int ni = 0; ni < 4; ni++) {
            const int n = col0 + warp_n*32 + ni*8 + qc*2;
            if (mode == 0) {
                const int h = n >> 6, d = n & 63;
                #pragma unroll
                for (int half = 0; half < 2; half++) {
                    const int m = m0 + half*8;
                    const int b = m >> 11, t = m & (NT-1);
                    const size_t idx = (((size_t)b*NH + h)*NT + t)*DH + d;
                    uint32_t hh, ll;
                    split_pack(acc[mi][ni][half*2], acc[mi][ni][half*2+1], hh, ll);
                    *(uint32_t*)&outh[idx] = hh;
                    *(uint32_t*)&outl[idx] = ll;
                }
            } else {
                const float2 bv = *(const float2*)(bias + n);
                #pragma unroll
                for (int half = 0; half < 2; half++) {
                    const int m = m0 + half*8;
                    float* o = Cout + (size_t)m*NC + n;
                    *(float2*)o = make_float2(acc[mi][ni][half*2] + bv.x,
                                              acc[mi][ni][half*2+1] + bv.y);
                }
            }
        }
    }
}

// ===========================================================================
// Tensor-core causal flash attention: cp.async double-buffered KV, one
// __syncthreads per tile, SW128 swizzle (128B rows: phys_chunk = c ^ (r&7)).
// Q staged through smem (overlapping KV stage 0), consumed into registers.
// ===========================================================================
#define APL 8192                // KV plane bytes: 64 rows * 128B
#define ASTAGE (4*APL)          // 32768 (kh, kl, vh, vl)
#define ATT_SMEM (2*ASTAGE)     // 65536; Q staging (2 x 16384) overlaps stage 0

__global__ __launch_bounds__(256) void attn_mma_kernel()
{
    extern __shared__ ush su[];

    const int tid  = threadIdx.x;
    const int wid  = tid >> 5;
    const int lane = tid & 31;
    const int qr = lane >> 2;
    const int qc = lane & 3;
    const int r0 = wid * 16;

    const int qt = gridDim.x - 1 - blockIdx.x;
    const int bh = blockIdx.y;

    const uint32_t sbase = (uint32_t)__cvta_generic_to_shared(su);

    // ---- stage Q (cp.async, swizzled 128B rows), then hoist fragments ----
    {
        const int lrq = tid >> 1;                 // 0..127
        const int cq0 = (tid & 1) * 4;            // chunks cq0..cq0+3
        const uint32_t sq = (uint32_t)lrq & 7;
        const size_t rowb = ((size_t)bh*NT + (size_t)qt*128 + lrq)*DH;
        const uint32_t dst = sbase + (uint32_t)lrq*128;
        #pragma unroll
        for (int i = 0; i < 4; i++) {
            const int cq = cq0 + i;
            const uint32_t ph = (uint32_t)((cq ^ sq) << 4);
            CP16(dst + ph,          g_qh + rowb + cq*8);
            CP16(dst + 16384 + ph,  g_ql + rowb + cq*8);
        }
        CP_COMMIT();
    }
    CP_WAIT0();
    __syncthreads();

    uint32_t Qh[4][4], Ql[4][4];
    {
        const uint32_t rq = (uint32_t)(r0 + (lane & 15));
        const uint32_t qa = sbase + rq*128 + ((((uint32_t)(lane >> 4)) ^ (rq & 7)) << 4);
        #pragma unroll
        for (int ks = 0; ks < 4; ks++) {
            const uint32_t a = qa ^ ((uint32_t)ks << 5);
            LDSM4(Qh[ks][0],Qh[ks][1],Qh[ks][2],Qh[ks][3], a);
            LDSM4(Ql[ks][0],Ql[ks][1],Ql[ks][2],Ql[ks][3], a + 16384);
        }
    }
    __syncthreads();   // all warps done reading Q smem (KV stage 0 overlaps it)

    // KV loader mapping: row lrk (0..63), chunks ck0=2*(tid&3), ck0+1
    const int lrk = tid >> 2;
    const int ck0 = (tid & 3) * 2;
    const uint32_t skl = (uint32_t)lrk & 7;
    const uint32_t kp0 = (uint32_t)((ck0     ^ skl) << 4);
    const uint32_t kp1 = (uint32_t)(((ck0+1) ^ skl) << 4);
    const uint32_t krowb = (uint32_t)lrk * 128;

    auto load_kv = [&](int kt, int s) {
        const size_t rowb = ((size_t)bh*NT + (size_t)kt*64 + lrk)*DH + ck0*8;
        const uint32_t st = sbase + (uint32_t)s*ASTAGE + krowb;
        CP16(st + kp0,          g_kh + rowb);  CP16(st + kp1,          g_kh + rowb + 8);
        CP16(st + APL + kp0,    g_kl + rowb);  CP16(st + APL + kp1,    g_kl + rowb + 8);
        CP16(st + 2*APL + kp0,  g_vh + rowb);  CP16(st + 2*APL + kp1,  g_vh + rowb + 8);
        CP16(st + 3*APL + kp0,  g_vl + rowb);  CP16(st + 3*APL + kp1,  g_vl + rowb + 8);
        CP_COMMIT();
    };

    // ldmatrix frag offsets (within a plane)
    const uint32_t rk = (uint32_t)(((lane & 16) >> 1) + (lane & 7));
    const uint32_t kf_off = rk*128 + ((((uint32_t)((lane & 8) >> 3)) ^ (rk & 7)) << 4);
    const uint32_t rv = (uint32_t)((lane & 8) + (lane & 7));
    const uint32_t vf_off = rv*128 + ((((uint32_t)((lane & 16) >> 4)) ^ (rv & 7)) << 4);

    float m_a = -1e30f, m_b = -1e30f, l_a = 0.0f, l_b = 0.0f;
    float O[8][4] = {};

    const int n_kv = 2*qt + 2;
    load_kv(0, 0);

    for (int kt = 0; kt < n_kv; kt++) {
        CP_WAIT0();          // this thread's copies for tile kt complete
        __syncthreads();     // all threads' waits done; all done computing kt-1
        if (kt + 1 < n_kv) load_kv(kt + 1, (kt + 1) & 1);

        const uint32_t stg = sbase + (uint32_t)(kt & 1)*ASTAGE;
        const uint32_t khp = stg, vhp = stg + 2*APL;

        // ---- S = Q K^T ----
        float S[8][4] = {};
        #pragma unroll
        for (int ks = 0; ks < 4; ks++) {
            const uint32_t kx = (uint32_t)ks << 5;
            #pragma unroll
            for (int np = 0; np < 4; np++) {
                uint32_t B0[4], B1[4];
                const uint32_t bo = (khp + kf_off + (uint32_t)np*2048) ^ kx;
                LDSM4(B0[0],B0[1],B0[2],B0[3], bo);
                LDSM4(B1[0],B1[1],B1[2],B1[3], bo + APL);
                #pragma unroll
                for (int j = 0; j < 2; j++) {
                    float* s = S[np*2 + j];
                    MMA_BF16(s, Qh[ks][0],Qh[ks][1],Qh[ks][2],Qh[ks][3], B0[j*2],B0[j*2+1]);
                    MMA_BF16(s, Ql[ks][0],Ql[ks][1],Ql[ks][2],Ql[ks][3], B0[j*2],B0[j*2+1]);
                    MMA_BF16(s, Qh[ks][0],Qh[ks][1],Qh[ks][2],Qh[ks][3], B1[j*2],B1[j*2+1]);
                }
            }
        }

        if (kt >= 2*qt) {   // causal mask (diagonal tiles only)
            const int ia = qt*128 + r0 + qr;
            #pragma unroll
            for (int nt = 0; nt < 8; nt++) {
                const int j0g = kt*64 + nt*8 + qc*2;
                if (j0g   > ia)   S[nt][0] = -1e30f;
                if (j0g+1 > ia)   S[nt][1] = -1e30f;
                if (j0g   > ia+8) S[nt][2] = -1e30f;
                if (j0g+1 > ia+8) S[nt][3] = -1e30f;
            }
        }

        // ---- online softmax (rows qr, qr+8) ----
        float mxa = -1e30f, mxb = -1e30f;
        #pragma unroll
        for (int nt = 0; nt < 8; nt++) {
            mxa = fmaxf(mxa, fmaxf(S[nt][0], S[nt][1]));
            mxb = fmaxf(mxb, fmaxf(S[nt][2], S[nt][3]));
        }
        mxa = fmaxf(mxa, __shfl_xor_sync(0xffffffffu, mxa, 1));
        mxa = fmaxf(mxa, __shfl_xor_sync(0xffffffffu, mxa, 2));
        mxb = fmaxf(mxb, __shfl_xor_sync(0xffffffffu, mxb, 1));
        mxb = fmaxf(mxb, __shfl_xor_sync(0xffffffffu, mxb, 2));
        const float mna = fmaxf(m_a, mxa), mnb = fmaxf(m_b, mxb);
        const float ala = __expf(m_a - mna), alb = __expf(m_b - mnb);
        float rsa = 0.0f, rsb = 0.0f;
        #pragma unroll
        for (int nt = 0; nt < 8; nt++) {
            S[nt][0] = __expf(S[nt][0] - mna);
            S[nt][1] = __expf(S[nt][1] - mna);
            S[nt][2] = __expf(S[nt][2] - mnb);
            S[nt][3] = __expf(S[nt][3] - mnb);
            rsa += S[nt][0] + S[nt][1];
            rsb += S[nt][2] + S[nt][3];
        }
        rsa += __shfl_xor_sync(0xffffffffu, rsa, 1);
        rsa += __shfl_xor_sync(0xffffffffu, rsa, 2);
        rsb += __shfl_xor_sync(0xffffffffu, rsb, 1);
        rsb += __shfl_xor_sync(0xffffffffu, rsb, 2);
        l_a = l_a * ala + rsa;  m_a = mna;
        l_b = l_b * alb + rsb;  m_b = mnb;
        #pragma unroll
        for (int nt = 0; nt < 8; nt++) {
            O[nt][0] *= ala; O[nt][1] *= ala;
            O[nt][2] *= alb; O[nt][3] *= alb;
        }

        // ---- O += P V : P in registers (accumulator -> A-fragment identity)
        #pragma unroll
        for (int ks = 0; ks < 4; ks++) {
            uint32_t ah[4], al[4];
            split_pack(S[2*ks][0],   S[2*ks][1],   ah[0], al[0]);
            split_pack(S[2*ks][2],   S[2*ks][3],   ah[1], al[1]);
            split_pack(S[2*ks+1][0], S[2*ks+1][1], ah[2], al[2]);
            split_pack(S[2*ks+1][2], S[2*ks+1][3], ah[3], al[3]);
            #pragma unroll
            for (int dp = 0; dp < 4; dp++) {
                uint32_t B0[4], B1[4];
                const uint32_t vo = (vhp + vf_off + (uint32_t)ks*2048) ^ ((uint32_t)dp << 5);
                LDSM4T(B0[0],B0[1],B0[2],B0[3], vo);
                LDSM4T(B1[0],B1[1],B1[2],B1[3], vo + APL);
                #pragma unroll
                for (int j = 0; j < 2; j++) {
                    float* o = O[dp*2 + j];
                    MMA_BF16(o, ah[0],ah[1],ah[2],ah[3], B0[j*2],B0[j*2+1]);
                    MMA_BF16(o, al[0],al[1],al[2],al[3], B0[j*2],B0[j*2+1]);
                    MMA_BF16(o, ah[0],ah[1],ah[2],ah[3], B1[j*2],B1[j*2+1]);
                }
            }
        }
    }

    // ---- epilogue: normalize, split, write hi/lo planes [B,T,H*HS] ----
    const int b = bh / NH, h = bh % NH;
    const float inva = 1.0f / l_a, invb = 1.0f / l_b;
    const int ta = qt*128 + r0 + qr;
    #pragma unroll
    for (int nt = 0; nt < 8; nt++) {
        const int d = nt*8 + qc*2;
        const size_t ia = ((size_t)b*NT + ta)*NC + h*DH + d;
        const size_t ib = ((size_t)b*NT + ta + 8)*NC + h*DH + d;
        uint32_t hh, ll;
        split_pack(O[nt][0]*inva, O[nt][1]*inva, hh, ll);
        *(uint32_t*)&g_ah[ia] = hh;  *(uint32_t*)&g_al[ia] = ll;
        split_pack(O[nt][2]*invb, O[nt][3]*invb, hh, ll);
        *(uint32_t*)&g_ah[ib] = hh;  *(uint32_t*)&g_al[ib] = ll;
    }
}

// ---------------------------------------------------------------------------

extern "C" void kernel_launch(void* const* d_in, const int* in_sizes, int n_in,
                              void* d_out, int out_size)
{
    const float* x  = (const float*)d_in[0];
    const float* Wq = (const float*)d_in[1];
    const float* Wk = (const float*)d_in[2];
    const float* Wv = (const float*)d_in[3];
    const float* Wo = (const float*)d_in[4];
    const float* bo = (const float*)d_in[5];
    float* out = (float*)d_out;

    cudaFuncSetAttribute(gemm_bf16,
                         cudaFuncAttributeMaxDynamicSharedMemorySize, GEMM_SMEM);
    cudaFuncSetAttribute(attn_mma_kernel,
                         cudaFuncAttributeMaxDynamicSharedMemorySize, ATT_SMEM);

    const int n4 = (int)(N4X + 4*N4W);
    convert_kernel<<< n4/256, 256 >>>(x, Wq, Wk, Wv, Wo);
    gemm_bf16<<< dim3(NC/BN, NM/BM, 3), 256, GEMM_SMEM >>>(nullptr, nullptr, 0);
    attn_mma_kernel<<< dim3(NT/128, NB*NH), 256, ATT_SMEM >>>();
    gemm_bf16<<< dim3(NC/BN, NM/BM, 1), 256, GEMM_SMEM >>>(bo, out, 1);
}